// round 1
// baseline (speedup 1.0000x reference)
#include <cuda_runtime.h>

#define G_SEG 20000
#define M_MEM 5120000
#define D_FEAT 256

// Per-glimpse accumulator: {sum_e, sum_e*px, sum_e*py, sum_e*pz}
// 20000 * 16B = 320 KB scratch (L2-resident).
__device__ float4 g_acc[G_SEG];

__global__ void zero_acc_kernel() {
    int i = blockIdx.x * blockDim.x + threadIdx.x;
    if (i < G_SEG) g_acc[i] = make_float4(0.f, 0.f, 0.f, 0.f);
}

// One vectorized reduction per member: red.global.add.v4.f32 (sm_90+).
__device__ __forceinline__ void red_v4(float4* p, float a, float b, float c, float d) {
    asm volatile("red.global.add.v4.f32 [%0], {%1, %2, %3, %4};"
                 :: "l"(p), "f"(a), "f"(b), "f"(c), "f"(d)
                 : "memory");
}

// Each thread handles 4 members: fully vectorized loads
// (1x float4 lm, 1x int4 idx, 3x float4 pos covering 12 floats).
__global__ __launch_bounds__(256) void member_kernel(
    const float4* __restrict__ pos4,
    const float4* __restrict__ lm4,
    const int4*   __restrict__ idx4)
{
    int t = blockIdx.x * blockDim.x + threadIdx.x;   // 0 .. M/4-1 (exact grid)

    float4 lm = lm4[t];
    int4   ix = idx4[t];
    float4 p0 = pos4[3 * t + 0];
    float4 p1 = pos4[3 * t + 1];
    float4 p2 = pos4[3 * t + 2];

    float e0 = __expf(lm.x);
    float e1 = __expf(lm.y);
    float e2 = __expf(lm.z);
    float e3 = __expf(lm.w);

    // member 0: (p0.x, p0.y, p0.z)
    red_v4(&g_acc[ix.x], e0, e0 * p0.x, e0 * p0.y, e0 * p0.z);
    // member 1: (p0.w, p1.x, p1.y)
    red_v4(&g_acc[ix.y], e1, e1 * p0.w, e1 * p1.x, e1 * p1.y);
    // member 2: (p1.z, p1.w, p2.x)
    red_v4(&g_acc[ix.z], e2, e2 * p1.z, e2 * p1.w, e2 * p2.x);
    // member 3: (p2.y, p2.z, p2.w)
    red_v4(&g_acc[ix.w], e3, e3 * p2.y, e3 * p2.z, e3 * p2.w);
}

// Warp-per-glimpse: GEMV row dot W (D=256: 2 float4 per lane), warp shfl
// reduce, then pointwise math + normalized center. Writes 5 floats per row.
__global__ __launch_bounds__(256) void finalize_kernel(
    const float* __restrict__ gf,     // (G, 256)
    const float* __restrict__ Wv,     // (256, 1)
    const float* __restrict__ bv,     // (1,)
    const float* __restrict__ u,      // (G,)
    const float* __restrict__ temp,   // scalar
    float* __restrict__ out)          // (G, 5)
{
    int gw   = (blockIdx.x * blockDim.x + threadIdx.x) >> 5;
    int lane = threadIdx.x & 31;
    if (gw >= G_SEG) return;

    const float4* row = (const float4*)(gf + (size_t)gw * D_FEAT);
    const float4* w4  = (const float4*)Wv;

    float s = 0.f;
#pragma unroll
    for (int k = 0; k < 2; k++) {
        float4 a = row[lane + 32 * k];
        float4 w = w4[lane + 32 * k];
        s += a.x * w.x + a.y * w.y + a.z * w.z + a.w * w.w;
    }
#pragma unroll
    for (int o = 16; o; o >>= 1) s += __shfl_xor_sync(0xFFFFFFFFu, s, o);

    if (lane == 0) {
        float logit = 8.8f * tanhf(s + bv[0]);
        float uu = u[gw];
        float relaxed = (logit + logf(uu) - log1pf(-uu)) / temp[0];
        // stable log-sigmoid
        float lzp = fminf(relaxed, 0.f) - log1pf(__expf(-fabsf(relaxed)));

        float4 acc = g_acc[gw];
        float inv = 1.f / acc.x;

        float* o5 = out + (size_t)gw * 5;
        o5[0] = lzp;
        o5[1] = logit;
        o5[2] = acc.y * inv;
        o5[3] = acc.z * inv;
        o5[4] = acc.w * inv;
    }
}

extern "C" void kernel_launch(void* const* d_in, const int* in_sizes, int n_in,
                              void* d_out, int out_size)
{
    const float* gf   = (const float*)d_in[0];   // glimpse_feature (G, 256)
    const float* pos  = (const float*)d_in[1];   // member_local_pos (M, 3)
    const float* lm   = (const float*)d_in[2];   // member_log_mask (M, 1)
    const int*   idx  = (const int*)  d_in[3];   // member_glimpse_index (M,)
    const float* u    = (const float*)d_in[4];   // u (G,)
    const float* Wv   = (const float*)d_in[5];   // W (256, 1)
    const float* bv   = (const float*)d_in[6];   // b (1,)
    const float* temp = (const float*)d_in[7];   // temperature scalar

    zero_acc_kernel<<<(G_SEG + 255) / 256, 256>>>();

    // M/4 = 1,280,000 work items, exactly 5000 blocks of 256.
    member_kernel<<<(M_MEM / 4) / 256, 256>>>(
        (const float4*)pos, (const float4*)lm, (const int4*)idx);

    finalize_kernel<<<(G_SEG * 32 + 255) / 256, 256>>>(
        gf, Wv, bv, u, temp, (float*)d_out);
}

// round 2
// speedup vs baseline: 1.1810x; 1.1810x over previous
#include <cuda_runtime.h>

#define G_SEG   20000
#define M_MEM   5120000
#define D_FEAT  256
#define R_REP   4

#define MEMBER_BLOCKS 5000            // (M/4)/256
#define GEMV_BLOCKS   2500            // 20000 warps / 8 warps per block

// Replicated per-glimpse accumulators: {sum_e, sum_e*px, sum_e*py, sum_e*pz}.
// 4 * 20000 * 16B = 1.25 MB, L2-resident. Zero-initialized at module load;
// finalize_kernel re-zeroes after reading, so every graph replay starts clean.
__device__ float4 g_acc[R_REP][G_SEG];

// One vectorized reduction per member: red.global.add.v4.f32 (sm_90+).
__device__ __forceinline__ void red_v4(float4* p, float a, float b, float c, float d) {
    asm volatile("red.global.add.v4.f32 [%0], {%1, %2, %3, %4};"
                 :: "l"(p), "f"(a), "f"(b), "f"(c), "f"(d)
                 : "memory");
}

// Fused kernel:
//   blocks [0, MEMBER_BLOCKS)                     -> member scatter-reduce
//   blocks [MEMBER_BLOCKS, MEMBER_BLOCKS+GEMV)    -> GEMV + presence logits
// The GEMV blocks stream 20.5 MB of glimpse features through otherwise-idle
// DRAM bandwidth while the member blocks saturate the LSU/L2-atomic path.
__global__ __launch_bounds__(256) void fused_kernel(
    const float4* __restrict__ pos4,
    const float4* __restrict__ lm4,
    const int4*   __restrict__ idx4,
    const float*  __restrict__ gf,     // (G, 256)
    const float*  __restrict__ Wv,     // (256,)
    const float*  __restrict__ bv,     // (1,)
    const float*  __restrict__ u,      // (G,)
    const float*  __restrict__ temp,   // scalar
    float*        __restrict__ out)    // (G, 5)
{
    if (blockIdx.x < MEMBER_BLOCKS) {
        int t = blockIdx.x * blockDim.x + threadIdx.x;   // 0 .. M/4-1 (exact)

        float4 lm = lm4[t];
        int4   ix = idx4[t];
        float4 p0 = pos4[3 * t + 0];
        float4 p1 = pos4[3 * t + 1];
        float4 p2 = pos4[3 * t + 2];

        float e0 = __expf(lm.x);
        float e1 = __expf(lm.y);
        float e2 = __expf(lm.z);
        float e3 = __expf(lm.w);

        // Per-warp replica choice interleaves replicas across the machine.
        int rep = ((blockIdx.x << 3) + (threadIdx.x >> 5)) & (R_REP - 1);
        float4* acc = g_acc[rep];

        red_v4(&acc[ix.x], e0, e0 * p0.x, e0 * p0.y, e0 * p0.z);
        red_v4(&acc[ix.y], e1, e1 * p0.w, e1 * p1.x, e1 * p1.y);
        red_v4(&acc[ix.z], e2, e2 * p1.z, e2 * p1.w, e2 * p2.x);
        red_v4(&acc[ix.w], e3, e3 * p2.y, e3 * p2.z, e3 * p2.w);
    } else {
        // Warp-per-glimpse GEMV: 8 warps/block.
        int gw   = (blockIdx.x - MEMBER_BLOCKS) * 8 + (threadIdx.x >> 5);
        int lane = threadIdx.x & 31;
        if (gw >= G_SEG) return;

        const float4* row = (const float4*)(gf + (size_t)gw * D_FEAT);
        const float4* w4  = (const float4*)Wv;

        float s = 0.f;
#pragma unroll
        for (int k = 0; k < 2; k++) {
            float4 a = row[lane + 32 * k];
            float4 w = w4[lane + 32 * k];
            s += a.x * w.x + a.y * w.y + a.z * w.z + a.w * w.w;
        }
#pragma unroll
        for (int o = 16; o; o >>= 1) s += __shfl_xor_sync(0xFFFFFFFFu, s, o);

        if (lane == 0) {
            float logit = 8.8f * tanhf(s + bv[0]);
            float uu = u[gw];
            float relaxed = (logit + logf(uu) - log1pf(-uu)) / temp[0];
            float lzp = fminf(relaxed, 0.f) - log1pf(__expf(-fabsf(relaxed)));
            float* o5 = out + (size_t)gw * 5;
            o5[0] = lzp;
            o5[1] = logit;
        }
    }
}

// Centers: sum replicas, normalize, write cols 2-4, and zero the replicas
// for the next graph replay.
__global__ __launch_bounds__(256) void finalize_kernel(float* __restrict__ out)
{
    int i = blockIdx.x * blockDim.x + threadIdx.x;
    if (i >= G_SEG) return;

    float4 s = make_float4(0.f, 0.f, 0.f, 0.f);
#pragma unroll
    for (int r = 0; r < R_REP; r++) {
        float4 a = g_acc[r][i];
        s.x += a.x; s.y += a.y; s.z += a.z; s.w += a.w;
        g_acc[r][i] = make_float4(0.f, 0.f, 0.f, 0.f);
    }

    float inv = 1.f / s.x;
    float* o5 = out + (size_t)i * 5;
    o5[2] = s.y * inv;
    o5[3] = s.z * inv;
    o5[4] = s.w * inv;
}

extern "C" void kernel_launch(void* const* d_in, const int* in_sizes, int n_in,
                              void* d_out, int out_size)
{
    const float* gf   = (const float*)d_in[0];   // glimpse_feature (G, 256)
    const float* pos  = (const float*)d_in[1];   // member_local_pos (M, 3)
    const float* lm   = (const float*)d_in[2];   // member_log_mask (M, 1)
    const int*   idx  = (const int*)  d_in[3];   // member_glimpse_index (M,)
    const float* u    = (const float*)d_in[4];   // u (G,)
    const float* Wv   = (const float*)d_in[5];   // W (256, 1)
    const float* bv   = (const float*)d_in[6];   // b (1,)
    const float* temp = (const float*)d_in[7];   // temperature scalar

    fused_kernel<<<MEMBER_BLOCKS + GEMV_BLOCKS, 256>>>(
        (const float4*)pos, (const float4*)lm, (const int4*)idx,
        gf, Wv, bv, u, temp, (float*)d_out);

    finalize_kernel<<<(G_SEG + 255) / 256, 256>>>((float*)d_out);
}